// round 1
// baseline (speedup 1.0000x reference)
#include <cuda_runtime.h>
#include <math.h>
#include <stdint.h>

// Problem constants
#define B_    4
#define N_    4096
#define DIM_  1024
#define H_    16
#define DH_   64
#define M_    32
#define R_    16384            // B_*N_ rows

// feature-map constants
#define NORMALIZER   0.35355339059327379f   // 64^-0.25
#define HALF_NORM2   0.0625f                // 0.5 * normalizer^2
#define RATIO        0.17677669529663689f   // 32^-0.5
#define EPS_         1e-4f

// Scratch layout (floats) in one big __device__ buffer
#define OFF_Q    ((size_t)0)
#define OFF_K    ((size_t)16777216)          // R_*DIM_
#define OFF_V    ((size_t)33554432)
#define OFF_ATTN ((size_t)50331648)
#define OFF_QF   ((size_t)67108864)          // 64*4096*32 = 8388608
#define OFF_TK   ((size_t)75497472)
#define OFF_CTX  ((size_t)83886080)          // 64*32*64 = 131072
#define OFF_KCS  ((size_t)84017152)          // 64*32 = 2048
#define OFF_KMAX ((size_t)84019200)          // 64
#define SCRATCH_FLOATS ((size_t)84019264)

__device__ float g_scratch[SCRATCH_FLOATS];

// ---------------------------------------------------------------------------
// init small accumulators
// ---------------------------------------------------------------------------
__global__ void init_kernel() {
    int i = blockIdx.x * blockDim.x + threadIdx.x;
    if (i < 131072) g_scratch[OFF_CTX + i] = 0.0f;
    if (i < 2048)   g_scratch[OFF_KCS + i] = 0.0f;
    if (i < 64)     g_scratch[OFF_KMAX + i] = -INFINITY;
}

// ---------------------------------------------------------------------------
// fp32 SIMT GEMM: C[MrowsxNcols] = A[MrowsxK] @ W[KxNcols] + bias
// 128x128 tile, BK=32, 256 threads, 8x8 per thread. Dims divide exactly.
// ---------------------------------------------------------------------------
__global__ void __launch_bounds__(256, 2)
gemm_kernel(const float* __restrict__ A, const float* __restrict__ W,
            const float* __restrict__ bias, float* __restrict__ C,
            int K, int Ncols) {
    __shared__ __align__(16) float As[32][128];
    __shared__ __align__(16) float Bs[32][128];
    const int tid = threadIdx.x;
    const int m0 = blockIdx.y * 128, n0 = blockIdx.x * 128;
    const int tx = tid & 15, ty = tid >> 4;

    float acc[8][8];
#pragma unroll
    for (int i = 0; i < 8; i++)
#pragma unroll
        for (int j = 0; j < 8; j++) acc[i][j] = 0.0f;

    for (int k0 = 0; k0 < K; k0 += 32) {
        // A tile: 128 rows x 32 k, transposed into As[k][row]
#pragma unroll
        for (int j = 0; j < 4; j++) {
            int v = tid + 256 * j;
            int row = v >> 3, kc = (v & 7) * 4;
            float4 a = *(const float4*)&A[(size_t)(m0 + row) * K + k0 + kc];
            As[kc + 0][row] = a.x;
            As[kc + 1][row] = a.y;
            As[kc + 2][row] = a.z;
            As[kc + 3][row] = a.w;
        }
        // B tile: 32 rows x 128 cols, direct
#pragma unroll
        for (int j = 0; j < 4; j++) {
            int v = tid + 256 * j;
            int row = v >> 5, nc = (v & 31) * 4;
            *(float4*)&Bs[row][nc] =
                *(const float4*)&W[(size_t)(k0 + row) * Ncols + n0 + nc];
        }
        __syncthreads();
#pragma unroll
        for (int kk = 0; kk < 32; kk++) {
            float4 a0 = *(const float4*)&As[kk][ty * 8];
            float4 a1 = *(const float4*)&As[kk][ty * 8 + 4];
            float4 b0 = *(const float4*)&Bs[kk][tx * 8];
            float4 b1 = *(const float4*)&Bs[kk][tx * 8 + 4];
            float av[8] = {a0.x, a0.y, a0.z, a0.w, a1.x, a1.y, a1.z, a1.w};
            float bv[8] = {b0.x, b0.y, b0.z, b0.w, b1.x, b1.y, b1.z, b1.w};
#pragma unroll
            for (int i = 0; i < 8; i++)
#pragma unroll
                for (int j = 0; j < 8; j++)
                    acc[i][j] = fmaf(av[i], bv[j], acc[i][j]);
        }
        __syncthreads();
    }

    float4 bias0 = *(const float4*)&bias[n0 + tx * 8];
    float4 bias1 = *(const float4*)&bias[n0 + tx * 8 + 4];
#pragma unroll
    for (int i = 0; i < 8; i++) {
        size_t o = (size_t)(m0 + ty * 8 + i) * Ncols + n0 + tx * 8;
        float4 c0 = make_float4(acc[i][0] + bias0.x, acc[i][1] + bias0.y,
                                acc[i][2] + bias0.z, acc[i][3] + bias0.w);
        float4 c1 = make_float4(acc[i][4] + bias1.x, acc[i][5] + bias1.y,
                                acc[i][6] + bias1.z, acc[i][7] + bias1.w);
        *(float4*)&C[o] = c0;
        *(float4*)&C[o + 4] = c1;
    }
}

// ---------------------------------------------------------------------------
// atomic float max via CAS
// ---------------------------------------------------------------------------
__device__ __forceinline__ void atomicMaxFloat(float* addr, float val) {
    int old = __float_as_int(*addr);
    while (__int_as_float(old) < val) {
        int assumed = old;
        old = atomicCAS((int*)addr, assumed, __float_as_int(val));
        if (old == assumed) break;
    }
}

// ---------------------------------------------------------------------------
// Feature kernels. One warp per (row, head).
// IS_Q: compute qf = ratio*(exp(dd - diag - rowmax) + eps), store to OFF_QF
// !IS_Q: store t = dd - diag to OFF_TK; atomicMax per-(b,h) max of dd
// ---------------------------------------------------------------------------
template <bool IS_Q>
__global__ void __launch_bounds__(128)
feat_kernel(const float* __restrict__ proj) {
    __shared__ float projT[2048];   // projT[d*32 + m]
    __shared__ float qv[4][64];
    const int tid = threadIdx.x;
#pragma unroll
    for (int i = tid; i < 2048; i += 128) {
        int mrow = i >> 6, d = i & 63;           // proj[m*64 + d]
        projT[d * 32 + mrow] = proj[i];
    }
    __syncthreads();

    const int wid = tid >> 5, lane = tid & 31;
    const int gw = blockIdx.x * 4 + wid;         // < R_*H_
    const int r = gw >> 4, h = gw & 15;
    const float* src =
        g_scratch + (IS_Q ? OFF_Q : OFF_K) + (size_t)r * DIM_ + h * DH_;
    qv[wid][lane] = src[lane];
    qv[wid][lane + 32] = src[lane + 32];
    __syncwarp();

    float acc = 0.0f, ss = 0.0f;
#pragma unroll
    for (int d = 0; d < 64; d++) {
        float qd = qv[wid][d];
        acc = fmaf(qd, projT[d * 32 + lane], acc);
        ss = fmaf(qd, qd, ss);
    }
    float dd = NORMALIZER * acc;                 // data_dash for m = lane
    float diag = HALF_NORM2 * ss;

    float wmax = dd;
#pragma unroll
    for (int off = 16; off > 0; off >>= 1)
        wmax = fmaxf(wmax, __shfl_xor_sync(0xffffffffu, wmax, off));

    const int b = r >> 12, n = r & 4095;
    const int bh = b * H_ + h;
    const size_t idx = ((size_t)bh * N_ + n) * M_ + lane;
    if (IS_Q) {
        g_scratch[OFF_QF + idx] = RATIO * (expf(dd - diag - wmax) + EPS_);
    } else {
        g_scratch[OFF_TK + idx] = dd - diag;
        if (lane == 0) atomicMaxFloat(&g_scratch[OFF_KMAX + bh], wmax);
    }
}

// ---------------------------------------------------------------------------
// Context + k_cumsum: per (b,h), ctx[m][e] = sum_n kf[n][m]*v[n][e],
// kcs[m] = sum_n kf[n][m].  Grid = 64 bh x 8 n-chunks of 512 rows.
// ---------------------------------------------------------------------------
__global__ void __launch_bounds__(256)
ctx_kernel(const unsigned char* __restrict__ mask) {
    __shared__ __align__(16) float kf_s[16][32];
    __shared__ __align__(16) float v_s[16][64];
    const int tid = threadIdx.x;
    const int bh = blockIdx.x >> 3, chunk = blockIdx.x & 7;
    const int b = bh >> 4, h = bh & 15;
    const float kmax = g_scratch[OFF_KMAX + bh];
    const int m = tid >> 3, eb = (tid & 7) * 8;

    float acc[8];
#pragma unroll
    for (int j = 0; j < 8; j++) acc[j] = 0.0f;
    float kcsl = 0.0f;

    const float* tk = g_scratch + OFF_TK + (size_t)bh * N_ * M_;
    const float* V = g_scratch + OFF_V;

    const int base = chunk * 512;
    for (int t0 = base; t0 < base + 512; t0 += 16) {
#pragma unroll
        for (int j = 0; j < 2; j++) {
            int lin = tid * 2 + j;
            int i = lin >> 5, mm = lin & 31;
            float tv = tk[(size_t)(t0 + i) * M_ + mm];
            kf_s[i][mm] = RATIO * (expf(tv - kmax) + EPS_);
        }
        {
            int i = tid >> 4, e4 = (tid & 15) * 4;
            int n = t0 + i;
            float4 v4 =
                *(const float4*)&V[(size_t)(b * N_ + n) * DIM_ + h * DH_ + e4];
            if (mask[b * N_ + n]) v4 = make_float4(0.f, 0.f, 0.f, 0.f);
            *(float4*)&v_s[i][e4] = v4;
        }
        __syncthreads();
#pragma unroll
        for (int i = 0; i < 16; i++) {
            float kfm = kf_s[i][m];
            kcsl += kfm;
#pragma unroll
            for (int j = 0; j < 8; j++)
                acc[j] = fmaf(kfm, v_s[i][eb + j], acc[j]);
        }
        __syncthreads();
    }

    float* ctx = g_scratch + OFF_CTX + (size_t)bh * (M_ * DH_);
#pragma unroll
    for (int j = 0; j < 8; j++) atomicAdd(&ctx[m * DH_ + eb + j], acc[j]);
    if ((tid & 7) == 0) atomicAdd(&g_scratch[OFF_KCS + bh * M_ + m], kcsl);
}

// ---------------------------------------------------------------------------
// Output head: out[n][e] = (1/(qf[n]·kcs)) * sum_m qf[n][m]*ctx[m][e]
// written merged-head into OFF_ATTN.  Grid = 64 bh x 8 chunks, 8 warps/block.
// ---------------------------------------------------------------------------
__global__ void __launch_bounds__(256)
outhead_kernel() {
    __shared__ float ctx_s[M_ * DH_];
    __shared__ float kcs_s[M_];
    const int tid = threadIdx.x;
    const int bh = blockIdx.x >> 3, chunk = blockIdx.x & 7;
    const int b = bh >> 4, h = bh & 15;
    for (int i = tid; i < M_ * DH_; i += 256)
        ctx_s[i] = g_scratch[OFF_CTX + (size_t)bh * (M_ * DH_) + i];
    if (tid < M_) kcs_s[tid] = g_scratch[OFF_KCS + bh * M_ + tid];
    __syncthreads();

    const int w = tid >> 5, lane = tid & 31;
    float* attn = g_scratch + OFF_ATTN;
    const float* qf = g_scratch + OFF_QF + (size_t)bh * N_ * M_;

    for (int rr = 0; rr < 64; rr++) {
        int n = chunk * 512 + w * 64 + rr;
        float ql = qf[(size_t)n * M_ + lane];
        float acc0 = 0.0f, acc1 = 0.0f, den = 0.0f;
#pragma unroll
        for (int mm = 0; mm < 32; mm++) {
            float qm = __shfl_sync(0xffffffffu, ql, mm);
            acc0 = fmaf(qm, ctx_s[mm * DH_ + lane], acc0);
            acc1 = fmaf(qm, ctx_s[mm * DH_ + 32 + lane], acc1);
            den = fmaf(qm, kcs_s[mm], den);
        }
        float dinv = 1.0f / den;
        size_t o = (size_t)(b * N_ + n) * DIM_ + h * DH_;
        attn[o + lane] = acc0 * dinv;
        attn[o + 32 + lane] = acc1 * dinv;
    }
}

// ---------------------------------------------------------------------------
// launch
// ---------------------------------------------------------------------------
extern "C" void kernel_launch(void* const* d_in, const int* in_sizes, int n_in,
                              void* d_out, int out_size) {
    (void)in_sizes; (void)n_in; (void)out_size;
    const float* x = (const float*)d_in[0];
    const unsigned char* mask = (const unsigned char*)d_in[1];
    const float* proj = (const float*)d_in[2];
    const float* Wq = (const float*)d_in[3];
    const float* bq = (const float*)d_in[4];
    const float* Wk = (const float*)d_in[5];
    const float* bk = (const float*)d_in[6];
    const float* Wv = (const float*)d_in[7];
    const float* bv = (const float*)d_in[8];
    const float* Wo = (const float*)d_in[9];
    const float* bo = (const float*)d_in[10];

    float* scratch = nullptr;
    cudaGetSymbolAddress((void**)&scratch, g_scratch);

    dim3 gg(DIM_ / 128, R_ / 128);   // (8, 128)
    init_kernel<<<512, 256>>>();
    gemm_kernel<<<gg, 256>>>(x, Wq, bq, scratch + OFF_Q, DIM_, DIM_);
    gemm_kernel<<<gg, 256>>>(x, Wk, bk, scratch + OFF_K, DIM_, DIM_);
    gemm_kernel<<<gg, 256>>>(x, Wv, bv, scratch + OFF_V, DIM_, DIM_);
    feat_kernel<true><<<R_ * H_ / 4, 128>>>(proj);
    feat_kernel<false><<<R_ * H_ / 4, 128>>>(proj);
    ctx_kernel<<<64 * 8, 256>>>(mask);
    outhead_kernel<<<64 * 8, 256>>>();
    gemm_kernel<<<gg, 256>>>(scratch + OFF_ATTN, Wo, bo, (float*)d_out,
                             DIM_, DIM_);
}

// round 2
// speedup vs baseline: 1.2986x; 1.2986x over previous
#include <cuda_runtime.h>
#include <math.h>
#include <stdint.h>

// Problem constants
#define B_    4
#define N_    4096
#define DIM_  1024
#define H_    16
#define DH_   64
#define M_    32
#define R_    16384            // B_*N_ rows

// feature-map constants
#define NORMALIZER   0.35355339059327379f   // 64^-0.25
#define HALF_NORM2   0.0625f                // 0.5 * normalizer^2
#define RATIO        0.17677669529663689f   // 32^-0.5
#define EPS_         1e-4f

// Scratch layout (floats) in one big __device__ buffer
#define OFF_Q    ((size_t)0)
#define OFF_K    ((size_t)16777216)          // R_*DIM_
#define OFF_V    ((size_t)33554432)
#define OFF_ATTN ((size_t)50331648)
#define OFF_QF   ((size_t)67108864)          // 64*4096*32 = 8388608
#define OFF_TK   ((size_t)75497472)
#define OFF_CTX  ((size_t)83886080)          // 64*32*64 = 131072
#define OFF_KCS  ((size_t)84017152)          // 64*32 = 2048
#define OFF_KMAX ((size_t)84019200)          // 64
#define SCRATCH_FLOATS ((size_t)84019264)

__device__ float g_scratch[SCRATCH_FLOATS];

// ---------------------------------------------------------------------------
// init small accumulators
// ---------------------------------------------------------------------------
__global__ void init_kernel() {
    int i = blockIdx.x * blockDim.x + threadIdx.x;
    if (i < 131072) g_scratch[OFF_CTX + i] = 0.0f;
    if (i < 2048)   g_scratch[OFF_KCS + i] = 0.0f;
    if (i < 64)     g_scratch[OFF_KMAX + i] = -INFINITY;
}

// ---------------------------------------------------------------------------
// TF32 helpers (3xTF32 split-precision GEMM)
// ---------------------------------------------------------------------------
__device__ __forceinline__ void f32_split(float x, uint32_t& hi, uint32_t& lo) {
    uint32_t h;
    asm("cvt.rna.tf32.f32 %0, %1;" : "=r"(h) : "f"(x));
    float r = x - __uint_as_float(h);
    uint32_t l;
    asm("cvt.rna.tf32.f32 %0, %1;" : "=r"(l) : "f"(r));
    hi = h; lo = l;
}

__device__ __forceinline__ void mma_tf32(float* c, const uint32_t* a,
                                         const uint32_t* b) {
    asm volatile(
        "mma.sync.aligned.m16n8k8.row.col.f32.tf32.tf32.f32 "
        "{%0,%1,%2,%3}, {%4,%5,%6,%7}, {%8,%9}, {%0,%1,%2,%3};"
        : "+f"(c[0]), "+f"(c[1]), "+f"(c[2]), "+f"(c[3])
        : "r"(a[0]), "r"(a[1]), "r"(a[2]), "r"(a[3]),
          "r"(b[0]), "r"(b[1]));
}

// ---------------------------------------------------------------------------
// Tensor-core GEMM: C[R x Nc] = A[R x K] @ W[K x Nc] + bias
// Block tile 128x128, BK=32, 256 threads = 8 warps in 4(m) x 2(n).
// Warp tile 32x64 = 2 m-frags x 8 n-frags of m16n8k8.
// 3xTF32: acc += Ahi*Bhi + Ahi*Blo + Alo*Bhi  (fp32-comparable accuracy).
// ---------------------------------------------------------------------------
#define AS_STRIDE 36     // banks of a-frag lanes: (4r+c)%32 all distinct
#define BS_STRIDE 136    // banks of b-frag lanes: (8k+n)%32 all distinct

__global__ void __launch_bounds__(256, 2)
gemm_tc_kernel(const float* __restrict__ A, const float* __restrict__ W,
               const float* __restrict__ bias, float* __restrict__ C,
               int K, int Ncols) {
    __shared__ __align__(16) float As[128 * AS_STRIDE];
    __shared__ __align__(16) float Bs[32 * BS_STRIDE];

    const int tid = threadIdx.x;
    const int lane = tid & 31, wid = tid >> 5;
    const int wm = wid & 3;            // warp m index (x32 rows)
    const int wn = wid >> 2;           // warp n index (x64 cols)
    const int m0 = blockIdx.y * 128, n0 = blockIdx.x * 128;
    const int grp = lane >> 2;         // 0..7
    const int tig = lane & 3;          // 0..3

    float acc[2][8][4];
#pragma unroll
    for (int mi = 0; mi < 2; mi++)
#pragma unroll
        for (int ni = 0; ni < 8; ni++)
#pragma unroll
            for (int j = 0; j < 4; j++) acc[mi][ni][j] = 0.0f;

    for (int k0 = 0; k0 < K; k0 += 32) {
        // A tile: 128 rows x 32 k
#pragma unroll
        for (int j = 0; j < 4; j++) {
            int v = tid + 256 * j;
            int row = v >> 3, kc = (v & 7) * 4;
            *(float4*)&As[row * AS_STRIDE + kc] =
                *(const float4*)&A[(size_t)(m0 + row) * K + k0 + kc];
        }
        // B tile: 32 k x 128 cols
#pragma unroll
        for (int j = 0; j < 4; j++) {
            int v = tid + 256 * j;
            int row = v >> 5, nc = (v & 31) * 4;
            *(float4*)&Bs[row * BS_STRIDE + nc] =
                *(const float4*)&W[(size_t)(k0 + row) * Ncols + n0 + nc];
        }
        __syncthreads();

#pragma unroll
        for (int kk = 0; kk < 32; kk += 8) {
            // ---- A fragments (2 m-frags), split hi/lo ----
            uint32_t ah[2][4], al[2][4];
#pragma unroll
            for (int mi = 0; mi < 2; mi++) {
                int r = wm * 32 + mi * 16 + grp;
                int c = kk + tig;
                float f0 = As[r * AS_STRIDE + c];
                float f1 = As[(r + 8) * AS_STRIDE + c];
                float f2 = As[r * AS_STRIDE + c + 4];
                float f3 = As[(r + 8) * AS_STRIDE + c + 4];
                f32_split(f0, ah[mi][0], al[mi][0]);
                f32_split(f1, ah[mi][1], al[mi][1]);
                f32_split(f2, ah[mi][2], al[mi][2]);
                f32_split(f3, ah[mi][3], al[mi][3]);
            }
            // ---- B fragments in chunks of 4 n-frags ----
#pragma unroll
            for (int nb = 0; nb < 8; nb += 4) {
                uint32_t bh[4][2], bl[4][2];
#pragma unroll
                for (int nj = 0; nj < 4; nj++) {
                    int col = wn * 64 + (nb + nj) * 8 + grp;
                    float g0 = Bs[(kk + tig) * BS_STRIDE + col];
                    float g1 = Bs[(kk + 4 + tig) * BS_STRIDE + col];
                    f32_split(g0, bh[nj][0], bl[nj][0]);
                    f32_split(g1, bh[nj][1], bl[nj][1]);
                }
#pragma unroll
                for (int mi = 0; mi < 2; mi++)
#pragma unroll
                    for (int nj = 0; nj < 4; nj++) {
                        float* c = acc[mi][nb + nj];
                        mma_tf32(c, ah[mi], bh[nj]);
                        mma_tf32(c, ah[mi], bl[nj]);
                        mma_tf32(c, al[mi], bh[nj]);
                    }
            }
        }
        __syncthreads();
    }

    // Epilogue: add bias, write fp32
#pragma unroll
    for (int ni = 0; ni < 8; ni++) {
        int col = n0 + wn * 64 + ni * 8 + tig * 2;
        float2 bv = *(const float2*)&bias[col];
#pragma unroll
        for (int mi = 0; mi < 2; mi++) {
            int row = m0 + wm * 32 + mi * 16 + grp;
            float2 c0 = make_float2(acc[mi][ni][0] + bv.x,
                                    acc[mi][ni][1] + bv.y);
            float2 c1 = make_float2(acc[mi][ni][2] + bv.x,
                                    acc[mi][ni][3] + bv.y);
            *(float2*)&C[(size_t)row * Ncols + col] = c0;
            *(float2*)&C[(size_t)(row + 8) * Ncols + col] = c1;
        }
    }
}

// ---------------------------------------------------------------------------
// atomic float max via CAS
// ---------------------------------------------------------------------------
__device__ __forceinline__ void atomicMaxFloat(float* addr, float val) {
    int old = __float_as_int(*addr);
    while (__int_as_float(old) < val) {
        int assumed = old;
        old = atomicCAS((int*)addr, assumed, __float_as_int(val));
        if (old == assumed) break;
    }
}

// ---------------------------------------------------------------------------
// Feature kernels. One warp per (row, head).
// ---------------------------------------------------------------------------
template <bool IS_Q>
__global__ void __launch_bounds__(128)
feat_kernel(const float* __restrict__ proj) {
    __shared__ float projT[2048];   // projT[d*32 + m]
    __shared__ float qv[4][64];
    const int tid = threadIdx.x;
#pragma unroll
    for (int i = tid; i < 2048; i += 128) {
        int mrow = i >> 6, d = i & 63;           // proj[m*64 + d]
        projT[d * 32 + mrow] = proj[i];
    }
    __syncthreads();

    const int wid = tid >> 5, lane = tid & 31;
    const int gw = blockIdx.x * 4 + wid;         // < R_*H_
    const int r = gw >> 4, h = gw & 15;
    const float* src =
        g_scratch + (IS_Q ? OFF_Q : OFF_K) + (size_t)r * DIM_ + h * DH_;
    qv[wid][lane] = src[lane];
    qv[wid][lane + 32] = src[lane + 32];
    __syncwarp();

    float acc = 0.0f, ss = 0.0f;
#pragma unroll
    for (int d = 0; d < 64; d++) {
        float qd = qv[wid][d];
        acc = fmaf(qd, projT[d * 32 + lane], acc);
        ss = fmaf(qd, qd, ss);
    }
    float dd = NORMALIZER * acc;                 // data_dash for m = lane
    float diag = HALF_NORM2 * ss;

    float wmax = dd;
#pragma unroll
    for (int off = 16; off > 0; off >>= 1)
        wmax = fmaxf(wmax, __shfl_xor_sync(0xffffffffu, wmax, off));

    const int b = r >> 12, n = r & 4095;
    const int bh = b * H_ + h;
    const size_t idx = ((size_t)bh * N_ + n) * M_ + lane;
    if (IS_Q) {
        g_scratch[OFF_QF + idx] = RATIO * (expf(dd - diag - wmax) + EPS_);
    } else {
        g_scratch[OFF_TK + idx] = dd - diag;
        if (lane == 0) atomicMaxFloat(&g_scratch[OFF_KMAX + bh], wmax);
    }
}

// ---------------------------------------------------------------------------
// Context + k_cumsum
// ---------------------------------------------------------------------------
__global__ void __launch_bounds__(256)
ctx_kernel(const unsigned char* __restrict__ mask) {
    __shared__ __align__(16) float kf_s[16][32];
    __shared__ __align__(16) float v_s[16][64];
    const int tid = threadIdx.x;
    const int bh = blockIdx.x >> 3, chunk = blockIdx.x & 7;
    const int b = bh >> 4, h = bh & 15;
    const float kmax = g_scratch[OFF_KMAX + bh];
    const int m = tid >> 3, eb = (tid & 7) * 8;

    float acc[8];
#pragma unroll
    for (int j = 0; j < 8; j++) acc[j] = 0.0f;
    float kcsl = 0.0f;

    const float* tk = g_scratch + OFF_TK + (size_t)bh * N_ * M_;
    const float* V = g_scratch + OFF_V;

    const int base = chunk * 512;
    for (int t0 = base; t0 < base + 512; t0 += 16) {
#pragma unroll
        for (int j = 0; j < 2; j++) {
            int lin = tid * 2 + j;
            int i = lin >> 5, mm = lin & 31;
            float tv = tk[(size_t)(t0 + i) * M_ + mm];
            kf_s[i][mm] = RATIO * (expf(tv - kmax) + EPS_);
        }
        {
            int i = tid >> 4, e4 = (tid & 15) * 4;
            int n = t0 + i;
            float4 v4 =
                *(const float4*)&V[(size_t)(b * N_ + n) * DIM_ + h * DH_ + e4];
            if (mask[b * N_ + n]) v4 = make_float4(0.f, 0.f, 0.f, 0.f);
            *(float4*)&v_s[i][e4] = v4;
        }
        __syncthreads();
#pragma unroll
        for (int i = 0; i < 16; i++) {
            float kfm = kf_s[i][m];
            kcsl += kfm;
#pragma unroll
            for (int j = 0; j < 8; j++)
                acc[j] = fmaf(kfm, v_s[i][eb + j], acc[j]);
        }
        __syncthreads();
    }

    float* ctx = g_scratch + OFF_CTX + (size_t)bh * (M_ * DH_);
#pragma unroll
    for (int j = 0; j < 8; j++) atomicAdd(&ctx[m * DH_ + eb + j], acc[j]);
    if ((tid & 7) == 0) atomicAdd(&g_scratch[OFF_KCS + bh * M_ + m], kcsl);
}

// ---------------------------------------------------------------------------
// Output head
// ---------------------------------------------------------------------------
__global__ void __launch_bounds__(256)
outhead_kernel() {
    __shared__ float ctx_s[M_ * DH_];
    __shared__ float kcs_s[M_];
    const int tid = threadIdx.x;
    const int bh = blockIdx.x >> 3, chunk = blockIdx.x & 7;
    const int b = bh >> 4, h = bh & 15;
    for (int i = tid; i < M_ * DH_; i += 256)
        ctx_s[i] = g_scratch[OFF_CTX + (size_t)bh * (M_ * DH_) + i];
    if (tid < M_) kcs_s[tid] = g_scratch[OFF_KCS + bh * M_ + tid];
    __syncthreads();

    const int w = tid >> 5, lane = tid & 31;
    float* attn = g_scratch + OFF_ATTN;
    const float* qf = g_scratch + OFF_QF + (size_t)bh * N_ * M_;

    for (int rr = 0; rr < 64; rr++) {
        int n = chunk * 512 + w * 64 + rr;
        float ql = qf[(size_t)n * M_ + lane];
        float acc0 = 0.0f, acc1 = 0.0f, den = 0.0f;
#pragma unroll
        for (int mm = 0; mm < 32; mm++) {
            float qm = __shfl_sync(0xffffffffu, ql, mm);
            acc0 = fmaf(qm, ctx_s[mm * DH_ + lane], acc0);
            acc1 = fmaf(qm, ctx_s[mm * DH_ + 32 + lane], acc1);
            den = fmaf(qm, kcs_s[mm], den);
        }
        float dinv = 1.0f / den;
        size_t o = (size_t)(b * N_ + n) * DIM_ + h * DH_;
        attn[o + lane] = acc0 * dinv;
        attn[o + 32 + lane] = acc1 * dinv;
    }
}

// ---------------------------------------------------------------------------
// launch
// ---------------------------------------------------------------------------
extern "C" void kernel_launch(void* const* d_in, const int* in_sizes, int n_in,
                              void* d_out, int out_size) {
    (void)in_sizes; (void)n_in; (void)out_size;
    const float* x = (const float*)d_in[0];
    const unsigned char* mask = (const unsigned char*)d_in[1];
    const float* proj = (const float*)d_in[2];
    const float* Wq = (const float*)d_in[3];
    const float* bq = (const float*)d_in[4];
    const float* Wk = (const float*)d_in[5];
    const float* bk = (const float*)d_in[6];
    const float* Wv = (const float*)d_in[7];
    const float* bv = (const float*)d_in[8];
    const float* Wo = (const float*)d_in[9];
    const float* bo = (const float*)d_in[10];

    float* scratch = nullptr;
    cudaGetSymbolAddress((void**)&scratch, g_scratch);

    dim3 gg(DIM_ / 128, R_ / 128);   // (8, 128)
    init_kernel<<<512, 256>>>();
    gemm_tc_kernel<<<gg, 256>>>(x, Wq, bq, scratch + OFF_Q, DIM_, DIM_);
    gemm_tc_kernel<<<gg, 256>>>(x, Wk, bk, scratch + OFF_K, DIM_, DIM_);
    gemm_tc_kernel<<<gg, 256>>>(x, Wv, bv, scratch + OFF_V, DIM_, DIM_);
    feat_kernel<true><<<R_ * H_ / 4, 128>>>(proj);
    feat_kernel<false><<<R_ * H_ / 4, 128>>>(proj);
    ctx_kernel<<<64 * 8, 256>>>(mask);
    outhead_kernel<<<64 * 8, 256>>>();
    gemm_tc_kernel<<<gg, 256>>>(scratch + OFF_ATTN, Wo, bo, (float*)d_out,
                                DIM_, DIM_);
}

// round 9
// speedup vs baseline: 2.4645x; 1.8978x over previous
#include <cuda_runtime.h>
#include <cuda_fp16.h>
#include <math.h>
#include <stdint.h>

// Problem constants
#define B_    4
#define N_    4096
#define DIM_  1024
#define H_    16
#define DH_   64
#define M_    32
#define R_    16384            // B_*N_ rows

// feature-map constants
#define NORMALIZER   0.35355339059327379f   // 64^-0.25
#define HALF_NORM2   0.0625f                // 0.5 * normalizer^2
#define RATIO        0.17677669529663689f   // 32^-0.5
#define EPS_         1e-4f

// f32 scratch (floats)
#define OFF_Q    ((size_t)0)
#define OFF_K    ((size_t)16777216)
#define OFF_V    ((size_t)33554432)
#define OFF_ATTN ((size_t)50331648)
#define OFF_QF   ((size_t)67108864)
#define OFF_TK   ((size_t)75497472)
#define OFF_CTX  ((size_t)83886080)
#define OFF_KCS  ((size_t)84017152)
#define OFF_KMAX ((size_t)84019200)
#define SCRATCH_FLOATS ((size_t)84019264)
__device__ float g_scratch[SCRATCH_FLOATS];

// fp16 split scratch (halves)
#define HX_HI ((size_t)0)
#define HX_LO ((size_t)16777216)
#define HA_HI ((size_t)33554432)
#define HA_LO ((size_t)50331648)
#define HW_BASE ((size_t)67108864)   // 8 x 1048576: qhi,qlo,khi,klo,vhi,vlo,ohi,olo
#define HALF_COUNT ((size_t)75497472)
__device__ __half g_half[HALF_COUNT];

// ---------------------------------------------------------------------------
// init small accumulators
// ---------------------------------------------------------------------------
__global__ void init_kernel() {
    int i = blockIdx.x * blockDim.x + threadIdx.x;
    if (i < 131072) g_scratch[OFF_CTX + i] = 0.0f;
    if (i < 2048)   g_scratch[OFF_KCS + i] = 0.0f;
    if (i < 64)     g_scratch[OFF_KMAX + i] = -INFINITY;
}

// ---------------------------------------------------------------------------
// fp16 split (row-major, vectorized by 4)
// ---------------------------------------------------------------------------
__global__ void split_kernel(const float* __restrict__ s, __half* __restrict__ hi,
                             __half* __restrict__ lo, int n) {
    int i = (blockIdx.x * blockDim.x + threadIdx.x) * 4;
    if (i >= n) return;
    float4 v = *(const float4*)(s + i);
    float vv[4] = {v.x, v.y, v.z, v.w};
    __half h[4], l[4];
#pragma unroll
    for (int j = 0; j < 4; j++) {
        h[j] = __float2half_rn(vv[j]);
        l[j] = __float2half_rn(vv[j] - __half2float(h[j]));
    }
    __half2* hp = (__half2*)(hi + i);
    hp[0] = __halves2half2(h[0], h[1]);
    hp[1] = __halves2half2(h[2], h[3]);
    __half2* lp = (__half2*)(lo + i);
    lp[0] = __halves2half2(l[0], l[1]);
    lp[1] = __halves2half2(l[2], l[3]);
}

// fp16 split + transpose for weights: W[k][n] -> hiT[n][k], loT[n][k]
__global__ void splitT_kernel(const float* __restrict__ W, __half* __restrict__ hiT,
                              __half* __restrict__ loT) {
    __shared__ float t[32][33];
    int tx = threadIdx.x, ty = threadIdx.y;
    int bn = blockIdx.x * 32, bk = blockIdx.y * 32;
    for (int j = ty; j < 32; j += 8)
        t[j][tx] = W[(size_t)(bk + j) * DIM_ + bn + tx];
    __syncthreads();
    for (int j = ty; j < 32; j += 8) {
        float v = t[tx][j];
        __half h = __float2half_rn(v);
        __half l = __float2half_rn(v - __half2float(h));
        hiT[(size_t)(bn + j) * DIM_ + bk + tx] = h;
        loT[(size_t)(bn + j) * DIM_ + bk + tx] = l;
    }
}

// ---------------------------------------------------------------------------
// fp16 HMMA m16n8k16 wrapper
// ---------------------------------------------------------------------------
__device__ __forceinline__ void mma_f16(float* c, const uint32_t* a,
                                        uint32_t b0, uint32_t b1) {
    asm volatile(
        "mma.sync.aligned.m16n8k16.row.col.f32.f16.f16.f32 "
        "{%0,%1,%2,%3}, {%4,%5,%6,%7}, {%8,%9}, {%0,%1,%2,%3};"
        : "+f"(c[0]), "+f"(c[1]), "+f"(c[2]), "+f"(c[3])
        : "r"(a[0]), "r"(a[1]), "r"(a[2]), "r"(a[3]), "r"(b0), "r"(b1));
}

// ---------------------------------------------------------------------------
// HMMA GEMM: C[R x 1024] = A[R x 1024] @ W[1024 x 1024] + bias
// A as fp16 hi/lo row-major [r][k]; W as fp16 hi/lo transposed [n][k].
// Block 128x128, BK=32, 256 threads = 8 warps (4m x 2n), warp tile 32x64.
// 3-pass split: acc += Ahi*Bhi + Ahi*Blo + Alo*Bhi.
// Smem stride 40 halves (20 words): (grp*20+tig)%32 all distinct -> no conflicts.
// ---------------------------------------------------------------------------
#define HS 40   // halves per smem row

__global__ void __launch_bounds__(256, 2)
gemm_hmma_kernel(const __half* __restrict__ Ahi, const __half* __restrict__ Alo,
                 const __half* __restrict__ Bhi, const __half* __restrict__ Blo,
                 const float* __restrict__ bias, float* __restrict__ C) {
    __shared__ __align__(16) __half Ah_s[128 * HS];
    __shared__ __align__(16) __half Al_s[128 * HS];
    __shared__ __align__(16) __half Bh_s[128 * HS];
    __shared__ __align__(16) __half Bl_s[128 * HS];

    const int tid = threadIdx.x;
    const int lane = tid & 31, wid = tid >> 5;
    const int wm = wid & 3;            // warp m index (x32 rows)
    const int wn = wid >> 2;           // warp n index (x64 cols)
    const int m0 = blockIdx.y * 128, n0 = blockIdx.x * 128;
    const int grp = lane >> 2;         // 0..7
    const int tig = lane & 3;          // 0..3

    const uint32_t* wAh = (const uint32_t*)Ah_s;
    const uint32_t* wAl = (const uint32_t*)Al_s;
    const uint32_t* wBh = (const uint32_t*)Bh_s;
    const uint32_t* wBl = (const uint32_t*)Bl_s;

    float acc[2][8][4];
#pragma unroll
    for (int mi = 0; mi < 2; mi++)
#pragma unroll
        for (int ni = 0; ni < 8; ni++)
#pragma unroll
            for (int j = 0; j < 4; j++) acc[mi][ni][j] = 0.0f;

    for (int k0 = 0; k0 < DIM_; k0 += 32) {
        // load 4 tiles: 128 rows x 32 halves each; 2 float4 per thread per tile
#pragma unroll
        for (int j = 0; j < 2; j++) {
            int id = tid + 256 * j;
            int row = id >> 2, c = (id & 3) * 8;
            size_t ga = (size_t)(m0 + row) * DIM_ + k0 + c;
            size_t gb = (size_t)(n0 + row) * DIM_ + k0 + c;
            *(float4*)&Ah_s[row * HS + c] = *(const float4*)&Ahi[ga];
            *(float4*)&Al_s[row * HS + c] = *(const float4*)&Alo[ga];
            *(float4*)&Bh_s[row * HS + c] = *(const float4*)&Bhi[gb];
            *(float4*)&Bl_s[row * HS + c] = *(const float4*)&Blo[gb];
        }
        __syncthreads();

#pragma unroll
        for (int ks = 0; ks < 2; ks++) {
            const int kw = ks * 8 + tig;       // word offset within row
            uint32_t ah[2][4], al[2][4];
#pragma unroll
            for (int mi = 0; mi < 2; mi++) {
                int rr = wm * 32 + mi * 16 + grp;
                ah[mi][0] = wAh[rr * 20 + kw];
                ah[mi][1] = wAh[(rr + 8) * 20 + kw];
                ah[mi][2] = wAh[rr * 20 + kw + 4];
                ah[mi][3] = wAh[(rr + 8) * 20 + kw + 4];
                al[mi][0] = wAl[rr * 20 + kw];
                al[mi][1] = wAl[(rr + 8) * 20 + kw];
                al[mi][2] = wAl[rr * 20 + kw + 4];
                al[mi][3] = wAl[(rr + 8) * 20 + kw + 4];
            }
#pragma unroll
            for (int nj = 0; nj < 8; nj++) {
                int cc = wn * 64 + nj * 8 + grp;
                uint32_t bh0 = wBh[cc * 20 + kw];
                uint32_t bh1 = wBh[cc * 20 + kw + 4];
                uint32_t bl0 = wBl[cc * 20 + kw];
                uint32_t bl1 = wBl[cc * 20 + kw + 4];
#pragma unroll
                for (int mi = 0; mi < 2; mi++) {
                    mma_f16(acc[mi][nj], ah[mi], bh0, bh1);
                    mma_f16(acc[mi][nj], ah[mi], bl0, bl1);
                    mma_f16(acc[mi][nj], al[mi], bh0, bh1);
                }
            }
        }
        __syncthreads();
    }

    // Epilogue: add bias, write fp32
#pragma unroll
    for (int ni = 0; ni < 8; ni++) {
        int col = n0 + wn * 64 + ni * 8 + tig * 2;
        float2 bv = *(const float2*)&bias[col];
#pragma unroll
        for (int mi = 0; mi < 2; mi++) {
            int row = m0 + wm * 32 + mi * 16 + grp;
            float2 c0 = make_float2(acc[mi][ni][0] + bv.x,
                                    acc[mi][ni][1] + bv.y);
            float2 c1 = make_float2(acc[mi][ni][2] + bv.x,
                                    acc[mi][ni][3] + bv.y);
            *(float2*)&C[(size_t)row * DIM_ + col] = c0;
            *(float2*)&C[(size_t)(row + 8) * DIM_ + col] = c1;
        }
    }
}

// ---------------------------------------------------------------------------
// atomic float max via CAS
// ---------------------------------------------------------------------------
__device__ __forceinline__ void atomicMaxFloat(float* addr, float val) {
    int old = __float_as_int(*addr);
    while (__int_as_float(old) < val) {
        int assumed = old;
        old = atomicCAS((int*)addr, assumed, __float_as_int(val));
        if (old == assumed) break;
    }
}

// ---------------------------------------------------------------------------
// Feature kernels. One warp per (row, head); 8 warps/block.
// proj in smem as [m][d] stride 68 -> LDS.128 per 4 d, conflict-free.
// ss via warp butterfly reduction.
// ---------------------------------------------------------------------------
template <bool IS_Q>
__global__ void __launch_bounds__(256)
feat_kernel(const float* __restrict__ proj) {
    __shared__ __align__(16) float projS[32 * 68];
    __shared__ __align__(16) float qv[8][64];
    const int tid = threadIdx.x;
    for (int i = tid; i < 2048; i += 256) {
        int mrow = i >> 6, d = i & 63;
        projS[mrow * 68 + d] = proj[i];
    }
    __syncthreads();

    const int wid = tid >> 5, lane = tid & 31;
    const int gw = blockIdx.x * 8 + wid;
    const int r = gw >> 4, h = gw & 15;
    const float* src =
        g_scratch + (IS_Q ? OFF_Q : OFF_K) + (size_t)r * DIM_ + h * DH_;
    float q0 = src[lane], q1 = src[lane + 32];
    qv[wid][lane] = q0;
    qv[wid][lane + 32] = q1;
    __syncwarp();

    float ss = fmaf(q0, q0, q1 * q1);
#pragma unroll
    for (int off = 16; off > 0; off >>= 1)
        ss += __shfl_xor_sync(0xffffffffu, ss, off);

    const float4* pr = (const float4*)&projS[lane * 68];
    const float4* qp = (const float4*)qv[wid];
    float acc = 0.0f;
#pragma unroll
    for (int d4 = 0; d4 < 16; d4++) {
        float4 p = pr[d4];
        float4 qd = qp[d4];
        acc = fmaf(p.x, qd.x, acc);
        acc = fmaf(p.y, qd.y, acc);
        acc = fmaf(p.z, qd.z, acc);
        acc = fmaf(p.w, qd.w, acc);
    }
    float dd = NORMALIZER * acc;
    float diag = HALF_NORM2 * ss;

    float wmax = dd;
#pragma unroll
    for (int off = 16; off > 0; off >>= 1)
        wmax = fmaxf(wmax, __shfl_xor_sync(0xffffffffu, wmax, off));

    const int b = r >> 12, n = r & 4095;
    const int bh = b * H_ + h;
    const size_t idx = ((size_t)bh * N_ + n) * M_ + lane;
    if (IS_Q) {
        g_scratch[OFF_QF + idx] = RATIO * (expf(dd - diag - wmax) + EPS_);
    } else {
        g_scratch[OFF_TK + idx] = dd - diag;
        if (lane == 0) atomicMaxFloat(&g_scratch[OFF_KMAX + bh], wmax);
    }
}

// ---------------------------------------------------------------------------
// Context + k_cumsum
// ---------------------------------------------------------------------------
__global__ void __launch_bounds__(256)
ctx_kernel(const unsigned char* __restrict__ mask) {
    __shared__ __align__(16) float kf_s[16][32];
    __shared__ __align__(16) float v_s[16][64];
    const int tid = threadIdx.x;
    const int bh = blockIdx.x >> 3, chunk = blockIdx.x & 7;
    const int b = bh >> 4, h = bh & 15;
    const float kmax = g_scratch[OFF_KMAX + bh];
    const int m = tid >> 3, eb = (tid & 7) * 8;

    float acc[8];
#pragma unroll
    for (int j = 0; j < 8; j++) acc[j] = 0.0f;
    float kcsl = 0.0f;

    const float* tk = g_scratch + OFF_TK + (size_t)bh * N_ * M_;
    const float* V = g_scratch + OFF_V;

    const int base = chunk * 512;
    for (int t0 = base; t0 < base + 512; t0 += 16) {
#pragma unroll
        for (int j = 0; j < 2; j++) {
            int lin = tid * 2 + j;
            int i = lin >> 5, mm = lin & 31;
            float tv = tk[(size_t)(t0 + i) * M_ + mm];
            kf_s[i][mm] = RATIO * (expf(tv - kmax) + EPS_);
        }
        {
            int i = tid >> 4, e4 = (tid & 15) * 4;
            int n = t0 + i;
            float4 v4 =
                *(const float4*)&V[(size_t)(b * N_ + n) * DIM_ + h * DH_ + e4];
            if (mask[b * N_ + n]) v4 = make_float4(0.f, 0.f, 0.f, 0.f);
            *(float4*)&v_s[i][e4] = v4;
        }
        __syncthreads();
#pragma unroll
        for (int i = 0; i < 16; i++) {
            float kfm = kf_s[i][m];
            kcsl += kfm;
#pragma unroll
            for (int j = 0; j < 8; j++)
                acc[j] = fmaf(kfm, v_s[i][eb + j], acc[j]);
        }
        __syncthreads();
    }

    float* ctx = g_scratch + OFF_CTX + (size_t)bh * (M_ * DH_);
#pragma unroll
    for (int j = 0; j < 8; j++) atomicAdd(&ctx[m * DH_ + eb + j], acc[j]);
    if ((tid & 7) == 0) atomicAdd(&g_scratch[OFF_KCS + bh * M_ + m], kcsl);
}

// ---------------------------------------------------------------------------
// Output head
// ---------------------------------------------------------------------------
__global__ void __launch_bounds__(256)
outhead_kernel() {
    __shared__ float ctx_s[M_ * DH_];
    __shared__ float kcs_s[M_];
    const int tid = threadIdx.x;
    const int bh = blockIdx.x >> 3, chunk = blockIdx.x & 7;
    const int b = bh >> 4, h = bh & 15;
    for (int i = tid; i < M_ * DH_; i += 256)
        ctx_s[i] = g_scratch[OFF_CTX + (size_t)bh * (M_ * DH_) + i];
    if (tid < M_) kcs_s[tid] = g_scratch[OFF_KCS + bh * M_ + tid];
    __syncthreads();

    const int w = tid >> 5, lane = tid & 31;
    float* attn = g_scratch + OFF_ATTN;
    const float* qf = g_scratch + OFF_QF + (size_t)bh * N_ * M_;

    for (int rr = 0; rr < 64; rr++) {
        int n = chunk * 512 + w * 64 + rr;
        float ql = qf[(size_t)n * M_ + lane];
        float acc0 = 0.0f, acc1 = 0.0f, den = 0.0f;
#pragma unroll
        for (int mm = 0; mm < 32; mm++) {
            float qm = __shfl_sync(0xffffffffu, ql, mm);
            acc0 = fmaf(qm, ctx_s[mm * DH_ + lane], acc0);
            acc1 = fmaf(qm, ctx_s[mm * DH_ + 32 + lane], acc1);
            den = fmaf(qm, kcs_s[mm], den);
        }
        float dinv = 1.0f / den;
        size_t o = (size_t)(b * N_ + n) * DIM_ + h * DH_;
        attn[o + lane] = acc0 * dinv;
        attn[o + 32 + lane] = acc1 * dinv;
    }
}

// ---------------------------------------------------------------------------
// launch
// ---------------------------------------------------------------------------
extern "C" void kernel_launch(void* const* d_in, const int* in_sizes, int n_in,
                              void* d_out, int out_size) {
    (void)in_sizes; (void)n_in; (void)out_size;
    const float* x = (const float*)d_in[0];
    const unsigned char* mask = (const unsigned char*)d_in[1];
    const float* proj = (const float*)d_in[2];
    const float* Wq = (const float*)d_in[3];
    const float* bq = (const float*)d_in[4];
    const float* Wk = (const float*)d_in[5];
    const float* bk = (const float*)d_in[6];
    const float* Wv = (const float*)d_in[7];
    const float* bv = (const float*)d_in[8];
    const float* Wo = (const float*)d_in[9];
    const float* bo = (const float*)d_in[10];

    float* scratch = nullptr;
    cudaGetSymbolAddress((void**)&scratch, g_scratch);
    __half* hs = nullptr;
    cudaGetSymbolAddress((void**)&hs, g_half);

    init_kernel<<<512, 256>>>();

    // split inputs
    split_kernel<<<R_ * DIM_ / 4 / 256, 256>>>(x, hs + HX_HI, hs + HX_LO,
                                               R_ * DIM_);
    dim3 tg(32, 32), tb(32, 8);
    splitT_kernel<<<tg, tb>>>(Wq, hs + HW_BASE + 0 * 1048576,
                              hs + HW_BASE + 1 * 1048576);
    splitT_kernel<<<tg, tb>>>(Wk, hs + HW_BASE + 2 * 1048576,
                              hs + HW_BASE + 3 * 1048576);
    splitT_kernel<<<tg, tb>>>(Wv, hs + HW_BASE + 4 * 1048576,
                              hs + HW_BASE + 5 * 1048576);
    splitT_kernel<<<tg, tb>>>(Wo, hs + HW_BASE + 6 * 1048576,
                              hs + HW_BASE + 7 * 1048576);

    dim3 gg(DIM_ / 128, R_ / 128);   // (8, 128)
    gemm_hmma_kernel<<<gg, 256>>>(
        hs + HX_HI, hs + HX_LO, hs + HW_BASE + 0 * 1048576,
        hs + HW_BASE + 1 * 1048576, bq, scratch + OFF_Q);
    gemm_hmma_kernel<<<gg, 256>>>(
        hs + HX_HI, hs + HX_LO, hs + HW_BASE + 2 * 1048576,
        hs + HW_BASE + 3 * 1048576, bk, scratch + OFF_K);
    gemm_hmma_kernel<<<gg, 256>>>(
        hs + HX_HI, hs + HX_LO, hs + HW_BASE + 4 * 1048576,
        hs + HW_BASE + 5 * 1048576, bv, scratch + OFF_V);

    feat_kernel<true><<<R_ * H_ / 8, 256>>>(proj);
    feat_kernel<false><<<R_ * H_ / 8, 256>>>(proj);
    ctx_kernel<<<64 * 8, 256>>>(mask);
    outhead_kernel<<<64 * 8, 256>>>();

    split_kernel<<<R_ * DIM_ / 4 / 256, 256>>>(scratch + OFF_ATTN, hs + HA_HI,
                                               hs + HA_LO, R_ * DIM_);
    gemm_hmma_kernel<<<gg, 256>>>(
        hs + HA_HI, hs + HA_LO, hs + HW_BASE + 6 * 1048576,
        hs + HW_BASE + 7 * 1048576, bo, (float*)d_out);
}

// round 10
// speedup vs baseline: 2.6739x; 1.0850x over previous
#include <cuda_runtime.h>
#include <cuda_fp16.h>
#include <math.h>
#include <stdint.h>

// Problem constants
#define B_    4
#define N_    4096
#define DIM_  1024
#define H_    16
#define DH_   64
#define M_    32
#define R_    16384            // B_*N_ rows

// feature-map constants
#define NORMALIZER   0.35355339059327379f   // 64^-0.25
#define HALF_NORM2   0.0625f                // 0.5 * normalizer^2
#define RATIO        0.17677669529663689f   // 32^-0.5
#define EPS_         1e-4f

// f32 scratch (floats)
#define OFF_Q    ((size_t)0)
#define OFF_K    ((size_t)16777216)
#define OFF_V    ((size_t)33554432)
#define OFF_QF   ((size_t)67108864)
#define OFF_TK   ((size_t)75497472)
#define OFF_CTX  ((size_t)83886080)
#define OFF_KCS  ((size_t)84017152)
#define OFF_KMAX ((size_t)84019200)
#define SCRATCH_FLOATS ((size_t)84019264)
__device__ float g_scratch[SCRATCH_FLOATS];

// fp16 split scratch (halves)
#define HX_HI ((size_t)0)
#define HX_LO ((size_t)16777216)
#define HA_HI ((size_t)33554432)
#define HA_LO ((size_t)50331648)
#define HW_BASE ((size_t)67108864)   // 8 x 1048576: qhi,qlo,khi,klo,vhi,vlo,ohi,olo
#define HALF_COUNT ((size_t)75497472)
__device__ __half g_half[HALF_COUNT];

// ---------------------------------------------------------------------------
// PTX helpers
// ---------------------------------------------------------------------------
__device__ __forceinline__ uint32_t smem_u32(const void* p) {
    uint32_t a;
    asm("{ .reg .u64 t; cvta.to.shared.u64 t, %1; cvt.u32.u64 %0, t; }"
        : "=r"(a) : "l"(p));
    return a;
}
__device__ __forceinline__ void cp_async16(uint32_t smem, const void* g) {
    asm volatile("cp.async.cg.shared.global [%0], [%1], 16;"
                 :: "r"(smem), "l"(g) : "memory");
}
#define CP_COMMIT() asm volatile("cp.async.commit_group;" ::: "memory")
#define CP_WAIT(n)  asm volatile("cp.async.wait_group %0;" :: "n"(n) : "memory")

// ---------------------------------------------------------------------------
// init small accumulators
// ---------------------------------------------------------------------------
__global__ void init_kernel() {
    int i = blockIdx.x * blockDim.x + threadIdx.x;
    if (i < 131072) g_scratch[OFF_CTX + i] = 0.0f;
    if (i < 2048)   g_scratch[OFF_KCS + i] = 0.0f;
    if (i < 64)     g_scratch[OFF_KMAX + i] = -INFINITY;
}

// ---------------------------------------------------------------------------
// fp16 split (row-major, vectorized by 4)
// ---------------------------------------------------------------------------
__global__ void split_kernel(const float* __restrict__ s, __half* __restrict__ hi,
                             __half* __restrict__ lo, int n) {
    int i = (blockIdx.x * blockDim.x + threadIdx.x) * 4;
    if (i >= n) return;
    float4 v = *(const float4*)(s + i);
    float vv[4] = {v.x, v.y, v.z, v.w};
    __half h[4], l[4];
#pragma unroll
    for (int j = 0; j < 4; j++) {
        h[j] = __float2half_rn(vv[j]);
        l[j] = __float2half_rn(vv[j] - __half2float(h[j]));
    }
    __half2* hp = (__half2*)(hi + i);
    hp[0] = __halves2half2(h[0], h[1]);
    hp[1] = __halves2half2(h[2], h[3]);
    __half2* lp = (__half2*)(lo + i);
    lp[0] = __halves2half2(l[0], l[1]);
    lp[1] = __halves2half2(l[2], l[3]);
}

// fp16 split + transpose for weights: W[k][n] -> hiT[n][k], loT[n][k]
__global__ void splitT_kernel(const float* __restrict__ W, __half* __restrict__ hiT,
                              __half* __restrict__ loT) {
    __shared__ float t[32][33];
    int tx = threadIdx.x, ty = threadIdx.y;
    int bn = blockIdx.x * 32, bk = blockIdx.y * 32;
    for (int j = ty; j < 32; j += 8)
        t[j][tx] = W[(size_t)(bk + j) * DIM_ + bn + tx];
    __syncthreads();
    for (int j = ty; j < 32; j += 8) {
        float v = t[tx][j];
        __half h = __float2half_rn(v);
        __half l = __float2half_rn(v - __half2float(h));
        hiT[(size_t)(bn + j) * DIM_ + bk + tx] = h;
        loT[(size_t)(bn + j) * DIM_ + bk + tx] = l;
    }
}

// ---------------------------------------------------------------------------
// fp16 HMMA m16n8k16 wrapper
// ---------------------------------------------------------------------------
__device__ __forceinline__ void mma_f16(float* c, const uint32_t* a,
                                        uint32_t b0, uint32_t b1) {
    asm volatile(
        "mma.sync.aligned.m16n8k16.row.col.f32.f16.f16.f32 "
        "{%0,%1,%2,%3}, {%4,%5,%6,%7}, {%8,%9}, {%0,%1,%2,%3};"
        : "+f"(c[0]), "+f"(c[1]), "+f"(c[2]), "+f"(c[3])
        : "r"(a[0]), "r"(a[1]), "r"(a[2]), "r"(a[3]), "r"(b0), "r"(b1));
}

// ---------------------------------------------------------------------------
// HMMA GEMM, cp.async 2-stage pipeline.
// C[R x 1024] = A[R x 1024] @ W[1024 x 1024] + bias
// A fp16 hi/lo row-major [r][k]; W fp16 hi/lo transposed [n][k].
// Block 128x128, BK=32, 256 threads = 8 warps (4m x 2n), warp tile 32x64.
// 3-pass split: acc += Ahi*Bhi + Ahi*Blo + Alo*Bhi.
// Smem row stride 40 halves (80 B, 16B-aligned): conflict-free fragments.
// Stage = 4 tiles x 128 x 40 halves = 40960 B; 2 stages = 81920 B dynamic.
// ---------------------------------------------------------------------------
#define TILE_H   5120                  // halves per tile (128*40)
#define STAGE_H  (4 * TILE_H)          // halves per stage
#define STAGE_B  (STAGE_H * 2)         // bytes per stage (40960)
#define GEMM_SMEM (2 * STAGE_B)        // 81920
#define NST 32                         // K / BK

__global__ void __launch_bounds__(256)
gemm_hmma_kernel(const __half* __restrict__ Ahi, const __half* __restrict__ Alo,
                 const __half* __restrict__ Bhi, const __half* __restrict__ Blo,
                 const float* __restrict__ bias, float* __restrict__ C) {
    extern __shared__ __align__(16) __half sm[];
    const uint32_t smb = smem_u32(sm);

    const int tid = threadIdx.x;
    const int lane = tid & 31, wid = tid >> 5;
    const int wm = wid & 3;            // warp m index (x32 rows)
    const int wn = wid >> 2;           // warp n index (x64 cols)
    const int m0 = blockIdx.y * 128, n0 = blockIdx.x * 128;
    const int grp = lane >> 2;         // 0..7
    const int tig = lane & 3;          // 0..3

    float acc[2][8][4];
#pragma unroll
    for (int mi = 0; mi < 2; mi++)
#pragma unroll
        for (int ni = 0; ni < 8; ni++)
#pragma unroll
            for (int j = 0; j < 4; j++) acc[mi][ni][j] = 0.0f;

    // stage loader: 4 tiles x 512 chunks of 16B; 8 cp.async per thread
    auto load_stage = [&](int sb, int k0) {
        uint32_t base = smb + sb * STAGE_B;
#pragma unroll
        for (int j = 0; j < 2; j++) {
            int id = tid + 256 * j;            // 0..511
            int row = id >> 2, ch = id & 3;
            uint32_t off = (uint32_t)(row * 80 + ch * 16);
            size_t ga = (size_t)(m0 + row) * DIM_ + k0 + ch * 8;
            size_t gb = (size_t)(n0 + row) * DIM_ + k0 + ch * 8;
            cp_async16(base + off, Ahi + ga);
            cp_async16(base + TILE_H * 2 + off, Alo + ga);
            cp_async16(base + 2 * TILE_H * 2 + off, Bhi + gb);
            cp_async16(base + 3 * TILE_H * 2 + off, Blo + gb);
        }
    };

    load_stage(0, 0);
    CP_COMMIT();

    for (int s = 0; s < NST; s++) {
        if (s + 1 < NST) {
            load_stage((s + 1) & 1, (s + 1) * 32);
            CP_COMMIT();
            CP_WAIT(1);
        } else {
            CP_WAIT(0);
        }
        __syncthreads();

        const uint32_t* wAh = (const uint32_t*)(sm + (s & 1) * STAGE_H);
        const uint32_t* wAl = wAh + TILE_H / 2;
        const uint32_t* wBh = wAh + TILE_H;
        const uint32_t* wBl = wAh + 3 * TILE_H / 2;

#pragma unroll
        for (int ks = 0; ks < 2; ks++) {
            const int kw = ks * 8 + tig;       // word offset within row
            uint32_t ah[2][4], al[2][4];
#pragma unroll
            for (int mi = 0; mi < 2; mi++) {
                int rr = wm * 32 + mi * 16 + grp;
                ah[mi][0] = wAh[rr * 20 + kw];
                ah[mi][1] = wAh[(rr + 8) * 20 + kw];
                ah[mi][2] = wAh[rr * 20 + kw + 4];
                ah[mi][3] = wAh[(rr + 8) * 20 + kw + 4];
                al[mi][0] = wAl[rr * 20 + kw];
                al[mi][1] = wAl[(rr + 8) * 20 + kw];
                al[mi][2] = wAl[rr * 20 + kw + 4];
                al[mi][3] = wAl[(rr + 8) * 20 + kw + 4];
            }
#pragma unroll
            for (int nj = 0; nj < 8; nj++) {
                int cc = wn * 64 + nj * 8 + grp;
                uint32_t bh0 = wBh[cc * 20 + kw];
                uint32_t bh1 = wBh[cc * 20 + kw + 4];
                uint32_t bl0 = wBl[cc * 20 + kw];
                uint32_t bl1 = wBl[cc * 20 + kw + 4];
#pragma unroll
                for (int mi = 0; mi < 2; mi++) {
                    mma_f16(acc[mi][nj], ah[mi], bh0, bh1);
                    mma_f16(acc[mi][nj], ah[mi], bl0, bl1);
                    mma_f16(acc[mi][nj], al[mi], bh0, bh1);
                }
            }
        }
        __syncthreads();
    }

    // Epilogue: add bias, write fp32
#pragma unroll
    for (int ni = 0; ni < 8; ni++) {
        int col = n0 + wn * 64 + ni * 8 + tig * 2;
        float2 bv = *(const float2*)&bias[col];
#pragma unroll
        for (int mi = 0; mi < 2; mi++) {
            int row = m0 + wm * 32 + mi * 16 + grp;
            float2 c0 = make_float2(acc[mi][ni][0] + bv.x,
                                    acc[mi][ni][1] + bv.y);
            float2 c1 = make_float2(acc[mi][ni][2] + bv.x,
                                    acc[mi][ni][3] + bv.y);
            *(float2*)&C[(size_t)row * DIM_ + col] = c0;
            *(float2*)&C[(size_t)(row + 8) * DIM_ + col] = c1;
        }
    }
}

// ---------------------------------------------------------------------------
// atomic float max via CAS
// ---------------------------------------------------------------------------
__device__ __forceinline__ void atomicMaxFloat(float* addr, float val) {
    int old = __float_as_int(*addr);
    while (__int_as_float(old) < val) {
        int assumed = old;
        old = atomicCAS((int*)addr, assumed, __float_as_int(val));
        if (old == assumed) break;
    }
}

// ---------------------------------------------------------------------------
// Feature kernels. One warp per (row, head); 8 warps/block.
// ---------------------------------------------------------------------------
template <bool IS_Q>
__global__ void __launch_bounds__(256)
feat_kernel(const float* __restrict__ proj) {
    __shared__ __align__(16) float projS[32 * 68];
    __shared__ __align__(16) float qv[8][64];
    const int tid = threadIdx.x;
    for (int i = tid; i < 2048; i += 256) {
        int mrow = i >> 6, d = i & 63;
        projS[mrow * 68 + d] = proj[i];
    }
    __syncthreads();

    const int wid = tid >> 5, lane = tid & 31;
    const int gw = blockIdx.x * 8 + wid;
    const int r = gw >> 4, h = gw & 15;
    const float* src =
        g_scratch + (IS_Q ? OFF_Q : OFF_K) + (size_t)r * DIM_ + h * DH_;
    float q0 = src[lane], q1 = src[lane + 32];
    qv[wid][lane] = q0;
    qv[wid][lane + 32] = q1;
    __syncwarp();

    float ss = fmaf(q0, q0, q1 * q1);
#pragma unroll
    for (int off = 16; off > 0; off >>= 1)
        ss += __shfl_xor_sync(0xffffffffu, ss, off);

    const float4* pr = (const float4*)&projS[lane * 68];
    const float4* qp = (const float4*)qv[wid];
    float acc = 0.0f;
#pragma unroll
    for (int d4 = 0; d4 < 16; d4++) {
        float4 p = pr[d4];
        float4 qd = qp[d4];
        acc = fmaf(p.x, qd.x, acc);
        acc = fmaf(p.y, qd.y, acc);
        acc = fmaf(p.z, qd.z, acc);
        acc = fmaf(p.w, qd.w, acc);
    }
    float dd = NORMALIZER * acc;
    float diag = HALF_NORM2 * ss;

    float wmax = dd;
#pragma unroll
    for (int off = 16; off > 0; off >>= 1)
        wmax = fmaxf(wmax, __shfl_xor_sync(0xffffffffu, wmax, off));

    const int b = r >> 12, n = r & 4095;
    const int bh = b * H_ + h;
    const size_t idx = ((size_t)bh * N_ + n) * M_ + lane;
    if (IS_Q) {
        g_scratch[OFF_QF + idx] = RATIO * (expf(dd - diag - wmax) + EPS_);
    } else {
        g_scratch[OFF_TK + idx] = dd - diag;
        if (lane == 0) atomicMaxFloat(&g_scratch[OFF_KMAX + bh], wmax);
    }
}

// ---------------------------------------------------------------------------
// Context + k_cumsum
// ---------------------------------------------------------------------------
__global__ void __launch_bounds__(256)
ctx_kernel(const unsigned char* __restrict__ mask) {
    __shared__ __align__(16) float kf_s[16][32];
    __shared__ __align__(16) float v_s[16][64];
    const int tid = threadIdx.x;
    const int bh = blockIdx.x >> 3, chunk = blockIdx.x & 7;
    const int b = bh >> 4, h = bh & 15;
    const float kmax = g_scratch[OFF_KMAX + bh];
    const int m = tid >> 3, eb = (tid & 7) * 8;

    float acc[8];
#pragma unroll
    for (int j = 0; j < 8; j++) acc[j] = 0.0f;
    float kcsl = 0.0f;

    const float* tk = g_scratch + OFF_TK + (size_t)bh * N_ * M_;
    const float* V = g_scratch + OFF_V;

    const int base = chunk * 512;
    for (int t0 = base; t0 < base + 512; t0 += 16) {
#pragma unroll
        for (int j = 0; j < 2; j++) {
            int lin = tid * 2 + j;
            int i = lin >> 5, mm = lin & 31;
            float tv = tk[(size_t)(t0 + i) * M_ + mm];
            kf_s[i][mm] = RATIO * (expf(tv - kmax) + EPS_);
        }
        {
            int i = tid >> 4, e4 = (tid & 15) * 4;
            int n = t0 + i;
            float4 v4 =
                *(const float4*)&V[(size_t)(b * N_ + n) * DIM_ + h * DH_ + e4];
            if (mask[b * N_ + n]) v4 = make_float4(0.f, 0.f, 0.f, 0.f);
            *(float4*)&v_s[i][e4] = v4;
        }
        __syncthreads();
#pragma unroll
        for (int i = 0; i < 16; i++) {
            float kfm = kf_s[i][m];
            kcsl += kfm;
#pragma unroll
            for (int j = 0; j < 8; j++)
                acc[j] = fmaf(kfm, v_s[i][eb + j], acc[j]);
        }
        __syncthreads();
    }

    float* ctx = g_scratch + OFF_CTX + (size_t)bh * (M_ * DH_);
#pragma unroll
    for (int j = 0; j < 8; j++) atomicAdd(&ctx[m * DH_ + eb + j], acc[j]);
    if ((tid & 7) == 0) atomicAdd(&g_scratch[OFF_KCS + bh * M_ + m], kcsl);
}

// ---------------------------------------------------------------------------
// Output head: writes attn directly as fp16 hi/lo (fuses the split)
// ---------------------------------------------------------------------------
__global__ void __launch_bounds__(256)
outhead_kernel(__half* __restrict__ Ohi, __half* __restrict__ Olo) {
    __shared__ float ctx_s[M_ * DH_];
    __shared__ float kcs_s[M_];
    const int tid = threadIdx.x;
    const int bh = blockIdx.x >> 3, chunk = blockIdx.x & 7;
    const int b = bh >> 4, h = bh & 15;
    for (int i = tid; i < M_ * DH_; i += 256)
        ctx_s[i] = g_scratch[OFF_CTX + (size_t)bh * (M_ * DH_) + i];
    if (tid < M_) kcs_s[tid] = g_scratch[OFF_KCS + bh * M_ + tid];
    __syncthreads();

    const int w = tid >> 5, lane = tid & 31;
    const float* qf = g_scratch + OFF_QF + (size_t)bh * N_ * M_;

    for (int rr = 0; rr < 64; rr++) {
        int n = chunk * 512 + w * 64 + rr;
        float ql = qf[(size_t)n * M_ + lane];
        float acc0 = 0.0f, acc1 = 0.0f, den = 0.0f;
#pragma unroll
        for (int mm = 0; mm < 32; mm++) {
            float qm = __shfl_sync(0xffffffffu, ql, mm);
            acc0 = fmaf(qm, ctx_s[mm * DH_ + lane], acc0);
            acc1 = fmaf(qm, ctx_s[mm * DH_ + 32 + lane], acc1);
            den = fmaf(qm, kcs_s[mm], den);
        }
        float dinv = 1.0f / den;
        float v0 = acc0 * dinv, v1 = acc1 * dinv;
        __half h0 = __float2half_rn(v0);
        __half h1 = __float2half_rn(v1);
        __half l0 = __float2half_rn(v0 - __half2float(h0));
        __half l1 = __float2half_rn(v1 - __half2float(h1));
        size_t o = (size_t)(b * N_ + n) * DIM_ + h * DH_;
        Ohi[o + lane] = h0;
        Ohi[o + 32 + lane] = h1;
        Olo[o + lane] = l0;
        Olo[o + 32 + lane] = l1;
    }
}

// ---------------------------------------------------------------------------
// launch (launch #6 = gemm Q for ncu visibility: capture is -s 5 -c 1)
// ---------------------------------------------------------------------------
extern "C" void kernel_launch(void* const* d_in, const int* in_sizes, int n_in,
                              void* d_out, int out_size) {
    (void)in_sizes; (void)n_in; (void)out_size;
    const float* x = (const float*)d_in[0];
    const unsigned char* mask = (const unsigned char*)d_in[1];
    const float* proj = (const float*)d_in[2];
    const float* Wq = (const float*)d_in[3];
    const float* bq = (const float*)d_in[4];
    const float* Wk = (const float*)d_in[5];
    const float* bk = (const float*)d_in[6];
    const float* Wv = (const float*)d_in[7];
    const float* bv = (const float*)d_in[8];
    const float* Wo = (const float*)d_in[9];
    const float* bo = (const float*)d_in[10];

    float* scratch = nullptr;
    cudaGetSymbolAddress((void**)&scratch, g_scratch);
    __half* hs = nullptr;
    cudaGetSymbolAddress((void**)&hs, g_half);

    cudaFuncSetAttribute(gemm_hmma_kernel,
                         cudaFuncAttributeMaxDynamicSharedMemorySize,
                         GEMM_SMEM);

    dim3 tg(32, 32), tb(32, 8);
    dim3 gg(DIM_ / 128, R_ / 128);   // (8, 128)

    init_kernel<<<512, 256>>>();                                        // 1
    split_kernel<<<R_ * DIM_ / 4 / 256, 256>>>(x, hs + HX_HI,
                                               hs + HX_LO, R_ * DIM_);  // 2
    splitT_kernel<<<tg, tb>>>(Wq, hs + HW_BASE + 0 * 1048576,
                              hs + HW_BASE + 1 * 1048576);              // 3
    splitT_kernel<<<tg, tb>>>(Wk, hs + HW_BASE + 2 * 1048576,
                              hs + HW_BASE + 3 * 1048576);              // 4
    splitT_kernel<<<tg, tb>>>(Wv, hs + HW_BASE + 4 * 1048576,
                              hs + HW_BASE + 5 * 1048576);              // 5
    gemm_hmma_kernel<<<gg, 256, GEMM_SMEM>>>(                           // 6 (ncu)
        hs + HX_HI, hs + HX_LO, hs + HW_BASE + 0 * 1048576,
        hs + HW_BASE + 1 * 1048576, bq, scratch + OFF_Q);
    gemm_hmma_kernel<<<gg, 256, GEMM_SMEM>>>(                           // 7
        hs + HX_HI, hs + HX_LO, hs + HW_BASE + 2 * 1048576,
        hs + HW_BASE + 3 * 1048576, bk, scratch + OFF_K);
    gemm_hmma_kernel<<<gg, 256, GEMM_SMEM>>>(                           // 8
        hs + HX_HI, hs + HX_LO, hs + HW_BASE + 4 * 1048576,
        hs + HW_BASE + 5 * 1048576, bv, scratch + OFF_V);
    feat_kernel<true><<<R_ * H_ / 8, 256>>>(proj);                      // 9
    feat_kernel<false><<<R_ * H_ / 8, 256>>>(proj);                     // 10
    ctx_kernel<<<64 * 8, 256>>>(mask);                                  // 11
    outhead_kernel<<<64 * 8, 256>>>(hs + HA_HI, hs + HA_LO);            // 12
    splitT_kernel<<<tg, tb>>>(Wo, hs + HW_BASE + 6 * 1048576,
                              hs + HW_BASE + 7 * 1048576);              // 13
    gemm_hmma_kernel<<<gg, 256, GEMM_SMEM>>>(                           // 14
        hs + HA_HI, hs + HA_LO, hs + HW_BASE + 6 * 1048576,
        hs + HW_BASE + 7 * 1048576, bo, (float*)d_out);
}

// round 11
// speedup vs baseline: 2.8153x; 1.0529x over previous
#include <cuda_runtime.h>
#include <cuda_fp16.h>
#include <math.h>
#include <stdint.h>

// Problem constants
#define B_    4
#define N_    4096
#define DIM_  1024
#define H_    16
#define DH_   64
#define M_    32
#define R_    16384            // B_*N_ rows

// feature-map constants
#define NORMALIZER   0.35355339059327379f   // 64^-0.25
#define HALF_NORM2   0.0625f                // 0.5 * normalizer^2
#define RATIO        0.17677669529663689f   // 32^-0.5
#define EPS_         1e-4f

// f32 scratch (floats)
#define OFF_V    ((size_t)33554432)
#define OFF_QF   ((size_t)67108864)
#define OFF_TK   ((size_t)75497472)
#define OFF_CTX  ((size_t)83886080)
#define OFF_KCS  ((size_t)84017152)
#define OFF_KMAX ((size_t)84019200)
#define SCRATCH_FLOATS ((size_t)84019264)
__device__ float g_scratch[SCRATCH_FLOATS];

// fp16 split scratch (halves)
#define HX_HI ((size_t)0)
#define HX_LO ((size_t)16777216)
#define HA_HI ((size_t)33554432)
#define HA_LO ((size_t)50331648)
#define HW_BASE ((size_t)67108864)   // 8 x 1048576: qhi,qlo,khi,klo,vhi,vlo,ohi,olo
#define HALF_COUNT ((size_t)75497472)
__device__ __half g_half[HALF_COUNT];

// ---------------------------------------------------------------------------
// PTX helpers
// ---------------------------------------------------------------------------
__device__ __forceinline__ uint32_t smem_u32(const void* p) {
    uint32_t a;
    asm("{ .reg .u64 t; cvta.to.shared.u64 t, %1; cvt.u32.u64 %0, t; }"
        : "=r"(a) : "l"(p));
    return a;
}
__device__ __forceinline__ void cp_async16(uint32_t smem, const void* g) {
    asm volatile("cp.async.cg.shared.global [%0], [%1], 16;"
                 :: "r"(smem), "l"(g) : "memory");
}
#define CP_COMMIT() asm volatile("cp.async.commit_group;" ::: "memory")
#define CP_WAIT(n)  asm volatile("cp.async.wait_group %0;" :: "n"(n) : "memory")

// ---------------------------------------------------------------------------
// init small accumulators
// ---------------------------------------------------------------------------
__global__ void init_kernel() {
    int i = blockIdx.x * blockDim.x + threadIdx.x;
    if (i < 131072) g_scratch[OFF_CTX + i] = 0.0f;
    if (i < 2048)   g_scratch[OFF_KCS + i] = 0.0f;
    if (i < 64)     g_scratch[OFF_KMAX + i] = -INFINITY;
}

// ---------------------------------------------------------------------------
// fp16 split (row-major, vectorized by 4)
// ---------------------------------------------------------------------------
__global__ void split_kernel(const float* __restrict__ s, __half* __restrict__ hi,
                             __half* __restrict__ lo, int n) {
    int i = (blockIdx.x * blockDim.x + threadIdx.x) * 4;
    if (i >= n) return;
    float4 v = *(const float4*)(s + i);
    float vv[4] = {v.x, v.y, v.z, v.w};
    __half h[4], l[4];
#pragma unroll
    for (int j = 0; j < 4; j++) {
        h[j] = __float2half_rn(vv[j]);
        l[j] = __float2half_rn(vv[j] - __half2float(h[j]));
    }
    __half2* hp = (__half2*)(hi + i);
    hp[0] = __halves2half2(h[0], h[1]);
    hp[1] = __halves2half2(h[2], h[3]);
    __half2* lp = (__half2*)(lo + i);
    lp[0] = __halves2half2(l[0], l[1]);
    lp[1] = __halves2half2(l[2], l[3]);
}

// fp16 split + transpose for weights: W[k][n] -> hiT[n][k], loT[n][k]
__global__ void splitT_kernel(const float* __restrict__ W, __half* __restrict__ hiT,
                              __half* __restrict__ loT) {
    __shared__ float t[32][33];
    int tx = threadIdx.x, ty = threadIdx.y;
    int bn = blockIdx.x * 32, bk = blockIdx.y * 32;
    for (int j = ty; j < 32; j += 8)
        t[j][tx] = W[(size_t)(bk + j) * DIM_ + bn + tx];
    __syncthreads();
    for (int j = ty; j < 32; j += 8) {
        float v = t[tx][j];
        __half h = __float2half_rn(v);
        __half l = __float2half_rn(v - __half2float(h));
        hiT[(size_t)(bn + j) * DIM_ + bk + tx] = h;
        loT[(size_t)(bn + j) * DIM_ + bk + tx] = l;
    }
}

// ---------------------------------------------------------------------------
// fp16 HMMA m16n8k16 wrapper
// ---------------------------------------------------------------------------
__device__ __forceinline__ void mma_f16(float* c, const uint32_t* a,
                                        uint32_t b0, uint32_t b1) {
    asm volatile(
        "mma.sync.aligned.m16n8k16.row.col.f32.f16.f16.f32 "
        "{%0,%1,%2,%3}, {%4,%5,%6,%7}, {%8,%9}, {%0,%1,%2,%3};"
        : "+f"(c[0]), "+f"(c[1]), "+f"(c[2]), "+f"(c[3])
        : "r"(a[0]), "r"(a[1]), "r"(a[2]), "r"(a[3]), "r"(b0), "r"(b1));
}

// ---------------------------------------------------------------------------
// atomic float max via CAS
// ---------------------------------------------------------------------------
__device__ __forceinline__ void atomicMaxFloat(float* addr, float val) {
    int old = __float_as_int(*addr);
    while (__int_as_float(old) < val) {
        int assumed = old;
        old = atomicCAS((int*)addr, assumed, __float_as_int(val));
        if (old == assumed) break;
    }
}

// ---------------------------------------------------------------------------
// HMMA GEMM, cp.async 2-stage pipeline + optional fused Performer features.
// MODE 0: C = A@W + bias -> out (fp32, R x 1024)
// MODE 1: q-feature epilogue -> out = QF[(bh*N+n)*32+m]
// MODE 2: k-feature epilogue -> out = TK (dd - diag); atomicMax kmax_g[bh]
// A fp16 hi/lo row-major [r][k]; W fp16 hi/lo transposed [n][k].
// Block 128x128, BK=32, 256 threads = 8 warps (4m x 2n), warp tile 32x64.
// 3-pass split: acc += Ahi*Bhi + Ahi*Blo + Alo*Bhi.
// Stage = 4 tiles x 128 x 40 halves = 40960 B; 2 stages dynamic.
// MODE 1/2: proj tile stored above the stages; after the mainloop the stage
// area is reused as a 128 x 132-padded fp32 C tile for feature computation.
// ---------------------------------------------------------------------------
#define TILE_H   5120                  // halves per tile (128*40)
#define STAGE_H  (4 * TILE_H)          // halves per stage
#define STAGE_B  (STAGE_H * 2)         // bytes per stage (40960)
#define SMEM0    (2 * STAGE_B)         // MODE 0: 81920
#define SMEM_F   (2 * STAGE_B + 8704)  // MODE 1/2: + projS 32*68 floats
#define NST 32                         // K / BK

template <int MODE>
__global__ void __launch_bounds__(256)
gemm_hmma_kernel(const __half* __restrict__ Ahi, const __half* __restrict__ Alo,
                 const __half* __restrict__ Bhi, const __half* __restrict__ Blo,
                 const float* __restrict__ bias, float* __restrict__ out,
                 const float* __restrict__ proj, float* __restrict__ kmax_g) {
    extern __shared__ __align__(16) __half sm[];
    const uint32_t smb = smem_u32(sm);
    __shared__ float s_hm[8];

    const int tid = threadIdx.x;
    const int lane = tid & 31, wid = tid >> 5;
    const int wm = wid & 3;            // warp m index (x32 rows)
    const int wn = wid >> 2;           // warp n index (x64 cols)
    const int m0 = blockIdx.y * 128, n0 = blockIdx.x * 128;
    const int grp = lane >> 2;         // 0..7
    const int tig = lane & 3;          // 0..3

    float* projS = (float*)(sm + STAGE_H * 2);   // [m][d] stride 68
    if (MODE != 0) {
        for (int i = tid; i < 2048; i += 256) {
            int mrow = i >> 6, d = i & 63;
            projS[mrow * 68 + d] = proj[i];
        }
    }

    float acc[2][8][4];
#pragma unroll
    for (int mi = 0; mi < 2; mi++)
#pragma unroll
        for (int ni = 0; ni < 8; ni++)
#pragma unroll
            for (int j = 0; j < 4; j++) acc[mi][ni][j] = 0.0f;

    auto load_stage = [&](int sb, int k0) {
        uint32_t base = smb + sb * STAGE_B;
#pragma unroll
        for (int j = 0; j < 2; j++) {
            int id = tid + 256 * j;            // 0..511
            int row = id >> 2, ch = id & 3;
            uint32_t off = (uint32_t)(row * 80 + ch * 16);
            size_t ga = (size_t)(m0 + row) * DIM_ + k0 + ch * 8;
            size_t gb = (size_t)(n0 + row) * DIM_ + k0 + ch * 8;
            cp_async16(base + off, Ahi + ga);
            cp_async16(base + TILE_H * 2 + off, Alo + ga);
            cp_async16(base + 2 * TILE_H * 2 + off, Bhi + gb);
            cp_async16(base + 3 * TILE_H * 2 + off, Blo + gb);
        }
    };

    load_stage(0, 0);
    CP_COMMIT();

    for (int s = 0; s < NST; s++) {
        if (s + 1 < NST) {
            load_stage((s + 1) & 1, (s + 1) * 32);
            CP_COMMIT();
            CP_WAIT(1);
        } else {
            CP_WAIT(0);
        }
        __syncthreads();

        const uint32_t* wAh = (const uint32_t*)(sm + (s & 1) * STAGE_H);
        const uint32_t* wAl = wAh + TILE_H / 2;
        const uint32_t* wBh = wAh + TILE_H;
        const uint32_t* wBl = wAh + 3 * TILE_H / 2;

#pragma unroll
        for (int ks = 0; ks < 2; ks++) {
            const int kw = ks * 8 + tig;
            uint32_t ah[2][4], al[2][4];
#pragma unroll
            for (int mi = 0; mi < 2; mi++) {
                int rr = wm * 32 + mi * 16 + grp;
                ah[mi][0] = wAh[rr * 20 + kw];
                ah[mi][1] = wAh[(rr + 8) * 20 + kw];
                ah[mi][2] = wAh[rr * 20 + kw + 4];
                ah[mi][3] = wAh[(rr + 8) * 20 + kw + 4];
                al[mi][0] = wAl[rr * 20 + kw];
                al[mi][1] = wAl[(rr + 8) * 20 + kw];
                al[mi][2] = wAl[rr * 20 + kw + 4];
                al[mi][3] = wAl[(rr + 8) * 20 + kw + 4];
            }
#pragma unroll
            for (int nj = 0; nj < 8; nj++) {
                int cc = wn * 64 + nj * 8 + grp;
                uint32_t bh0 = wBh[cc * 20 + kw];
                uint32_t bh1 = wBh[cc * 20 + kw + 4];
                uint32_t bl0 = wBl[cc * 20 + kw];
                uint32_t bl1 = wBl[cc * 20 + kw + 4];
#pragma unroll
                for (int mi = 0; mi < 2; mi++) {
                    mma_f16(acc[mi][nj], ah[mi], bh0, bh1);
                    mma_f16(acc[mi][nj], ah[mi], bl0, bl1);
                    mma_f16(acc[mi][nj], al[mi], bh0, bh1);
                }
            }
        }
        __syncthreads();
    }

    if (MODE == 0) {
        // Plain epilogue: add bias, write fp32
#pragma unroll
        for (int ni = 0; ni < 8; ni++) {
            int col = n0 + wn * 64 + ni * 8 + tig * 2;
            float2 bv = *(const float2*)&bias[col];
#pragma unroll
            for (int mi = 0; mi < 2; mi++) {
                int row = m0 + wm * 32 + mi * 16 + grp;
                float2 c0 = make_float2(acc[mi][ni][0] + bv.x,
                                        acc[mi][ni][1] + bv.y);
                float2 c1 = make_float2(acc[mi][ni][2] + bv.x,
                                        acc[mi][ni][3] + bv.y);
                *(float2*)&out[(size_t)row * DIM_ + col] = c0;
                *(float2*)&out[(size_t)(row + 8) * DIM_ + col] = c1;
            }
        }
        return;
    }

    // -------- fused feature epilogue (MODE 1 = q, MODE 2 = k) --------
    float* Cs = (float*)sm;   // 128 x 132 fp32 tile, reuses stage area
#pragma unroll
    for (int ni = 0; ni < 8; ni++) {
        int col = wn * 64 + ni * 8 + tig * 2;
        float2 bv = *(const float2*)&bias[n0 + col];
#pragma unroll
        for (int mi = 0; mi < 2; mi++) {
            int row = wm * 32 + mi * 16 + grp;
            Cs[row * 132 + col] = acc[mi][ni][0] + bv.x;
            Cs[row * 132 + col + 1] = acc[mi][ni][1] + bv.y;
            Cs[(row + 8) * 132 + col] = acc[mi][ni][2] + bv.x;
            Cs[(row + 8) * 132 + col + 1] = acc[mi][ni][3] + bv.y;
        }
    }
    __syncthreads();

    const int hh = wid & 1;                    // head within tile
    const int head = blockIdx.x * 2 + hh;      // global head
    const int b = m0 >> 12;                    // batch (constant per block)
    const int bh = b * H_ + head;
    const int r0 = (wid >> 1) * 32;            // 4 warp-groups x 32 rows
    const float4* pr = (const float4*)&projS[lane * 68];
    float kmaxw = -INFINITY;

    for (int rr = r0; rr < r0 + 32; rr++) {
        const float* qrow = &Cs[rr * 132 + hh * 64];
        float q0 = qrow[lane], q1 = qrow[lane + 32];
        float ss = fmaf(q0, q0, q1 * q1);
#pragma unroll
        for (int off = 16; off > 0; off >>= 1)
            ss += __shfl_xor_sync(0xffffffffu, ss, off);

        const float4* qp = (const float4*)qrow;
        float accd = 0.0f;
#pragma unroll
        for (int d4 = 0; d4 < 16; d4++) {
            float4 p = pr[d4];
            float4 qd = qp[d4];
            accd = fmaf(p.x, qd.x, accd);
            accd = fmaf(p.y, qd.y, accd);
            accd = fmaf(p.z, qd.z, accd);
            accd = fmaf(p.w, qd.w, accd);
        }
        float dd = NORMALIZER * accd;          // data_dash at m = lane
        float diag = HALF_NORM2 * ss;

        float wmax = dd;
#pragma unroll
        for (int off = 16; off > 0; off >>= 1)
            wmax = fmaxf(wmax, __shfl_xor_sync(0xffffffffu, wmax, off));

        const int n = (m0 + rr) & 4095;
        const size_t idx = ((size_t)bh * N_ + n) * M_ + lane;
        if (MODE == 1) {
            out[idx] = RATIO * (expf(dd - diag - wmax) + EPS_);
        } else {
            out[idx] = dd - diag;
            kmaxw = fmaxf(kmaxw, wmax);
        }
    }

    if (MODE == 2) {
        if (lane == 0) s_hm[wid] = kmaxw;
        __syncthreads();
        if (tid < 2) {
            float m4 = fmaxf(fmaxf(s_hm[tid], s_hm[tid + 2]),
                             fmaxf(s_hm[tid + 4], s_hm[tid + 6]));
            atomicMaxFloat(&kmax_g[b * H_ + blockIdx.x * 2 + tid], m4);
        }
    }
}

// ---------------------------------------------------------------------------
// Context + k_cumsum
// ---------------------------------------------------------------------------
__global__ void __launch_bounds__(256)
ctx_kernel(const unsigned char* __restrict__ mask) {
    __shared__ __align__(16) float kf_s[16][32];
    __shared__ __align__(16) float v_s[16][64];
    const int tid = threadIdx.x;
    const int bh = blockIdx.x >> 3, chunk = blockIdx.x & 7;
    const int b = bh >> 4, h = bh & 15;
    const float kmax = g_scratch[OFF_KMAX + bh];
    const int m = tid >> 3, eb = (tid & 7) * 8;

    float acc[8];
#pragma unroll
    for (int j = 0; j < 8; j++) acc[j] = 0.0f;
    float kcsl = 0.0f;

    const float* tk = g_scratch + OFF_TK + (size_t)bh * N_ * M_;
    const float* V = g_scratch + OFF_V;

    const int base = chunk * 512;
    for (int t0 = base; t0 < base + 512; t0 += 16) {
#pragma unroll
        for (int j = 0; j < 2; j++) {
            int lin = tid * 2 + j;
            int i = lin >> 5, mm = lin & 31;
            float tv = tk[(size_t)(t0 + i) * M_ + mm];
            kf_s[i][mm] = RATIO * (expf(tv - kmax) + EPS_);
        }
        {
            int i = tid >> 4, e4 = (tid & 15) * 4;
            int n = t0 + i;
            float4 v4 =
                *(const float4*)&V[(size_t)(b * N_ + n) * DIM_ + h * DH_ + e4];
            if (mask[b * N_ + n]) v4 = make_float4(0.f, 0.f, 0.f, 0.f);
            *(float4*)&v_s[i][e4] = v4;
        }
        __syncthreads();
#pragma unroll
        for (int i = 0; i < 16; i++) {
            float kfm = kf_s[i][m];
            kcsl += kfm;
#pragma unroll
            for (int j = 0; j < 8; j++)
                acc[j] = fmaf(kfm, v_s[i][eb + j], acc[j]);
        }
        __syncthreads();
    }

    float* ctx = g_scratch + OFF_CTX + (size_t)bh * (M_ * DH_);
#pragma unroll
    for (int j = 0; j < 8; j++) atomicAdd(&ctx[m * DH_ + eb + j], acc[j]);
    if ((tid & 7) == 0) atomicAdd(&g_scratch[OFF_KCS + bh * M_ + m], kcsl);
}

// ---------------------------------------------------------------------------
// Output head: writes attn directly as fp16 hi/lo (fused split)
// ---------------------------------------------------------------------------
__global__ void __launch_bounds__(256)
outhead_kernel(__half* __restrict__ Ohi, __half* __restrict__ Olo) {
    __shared__ float ctx_s[M_ * DH_];
    __shared__ float kcs_s[M_];
    const int tid = threadIdx.x;
    const int bh = blockIdx.x >> 3, chunk = blockIdx.x & 7;
    const int b = bh >> 4, h = bh & 15;
    for (int i = tid; i < M_ * DH_; i += 256)
        ctx_s[i] = g_scratch[OFF_CTX + (size_t)bh * (M_ * DH_) + i];
    if (tid < M_) kcs_s[tid] = g_scratch[OFF_KCS + bh * M_ + tid];
    __syncthreads();

    const int w = tid >> 5, lane = tid & 31;
    const float* qf = g_scratch + OFF_QF + (size_t)bh * N_ * M_;

    for (int rr = 0; rr < 64; rr++) {
        int n = chunk * 512 + w * 64 + rr;
        float ql = qf[(size_t)n * M_ + lane];
        float acc0 = 0.0f, acc1 = 0.0f, den = 0.0f;
#pragma unroll
        for (int mm = 0; mm < 32; mm++) {
            float qm = __shfl_sync(0xffffffffu, ql, mm);
            acc0 = fmaf(qm, ctx_s[mm * DH_ + lane], acc0);
            acc1 = fmaf(qm, ctx_s[mm * DH_ + 32 + lane], acc1);
            den = fmaf(qm, kcs_s[mm], den);
        }
        float dinv = 1.0f / den;
        float v0 = acc0 * dinv, v1 = acc1 * dinv;
        __half h0 = __float2half_rn(v0);
        __half h1 = __float2half_rn(v1);
        __half l0 = __float2half_rn(v0 - __half2float(h0));
        __half l1 = __float2half_rn(v1 - __half2float(h1));
        size_t o = (size_t)(b * N_ + n) * DIM_ + h * DH_;
        Ohi[o + lane] = h0;
        Ohi[o + 32 + lane] = h1;
        Olo[o + lane] = l0;
        Olo[o + 32 + lane] = l1;
    }
}

// ---------------------------------------------------------------------------
// launch
// ---------------------------------------------------------------------------
extern "C" void kernel_launch(void* const* d_in, const int* in_sizes, int n_in,
                              void* d_out, int out_size) {
    (void)in_sizes; (void)n_in; (void)out_size;
    const float* x = (const float*)d_in[0];
    const unsigned char* mask = (const unsigned char*)d_in[1];
    const float* proj = (const float*)d_in[2];
    const float* Wq = (const float*)d_in[3];
    const float* bq = (const float*)d_in[4];
    const float* Wk = (const float*)d_in[5];
    const float* bk = (const float*)d_in[6];
    const float* Wv = (const float*)d_in[7];
    const float* bv = (const float*)d_in[8];
    const float* Wo = (const float*)d_in[9];
    const float* bo = (const float*)d_in[10];

    float* scratch = nullptr;
    cudaGetSymbolAddress((void**)&scratch, g_scratch);
    __half* hs = nullptr;
    cudaGetSymbolAddress((void**)&hs, g_half);

    cudaFuncSetAttribute(gemm_hmma_kernel<0>,
                         cudaFuncAttributeMaxDynamicSharedMemorySize, SMEM0);
    cudaFuncSetAttribute(gemm_hmma_kernel<1>,
                         cudaFuncAttributeMaxDynamicSharedMemorySize, SMEM_F);
    cudaFuncSetAttribute(gemm_hmma_kernel<2>,
                         cudaFuncAttributeMaxDynamicSharedMemorySize, SMEM_F);

    dim3 tg(32, 32), tb(32, 8);
    dim3 gg(DIM_ / 128, R_ / 128);   // (8, 128)

    init_kernel<<<512, 256>>>();
    split_kernel<<<R_ * DIM_ / 4 / 256, 256>>>(x, hs + HX_HI,
                                               hs + HX_LO, R_ * DIM_);
    splitT_kernel<<<tg, tb>>>(Wq, hs + HW_BASE + 0 * 1048576,
                              hs + HW_BASE + 1 * 1048576);
    splitT_kernel<<<tg, tb>>>(Wk, hs + HW_BASE + 2 * 1048576,
                              hs + HW_BASE + 3 * 1048576);
    splitT_kernel<<<tg, tb>>>(Wv, hs + HW_BASE + 4 * 1048576,
                              hs + HW_BASE + 5 * 1048576);

    // Q GEMM + fused q-feature
    gemm_hmma_kernel<1><<<gg, 256, SMEM_F>>>(
        hs + HX_HI, hs + HX_LO, hs + HW_BASE + 0 * 1048576,
        hs + HW_BASE + 1 * 1048576, bq, scratch + OFF_QF, proj, nullptr);
    // K GEMM + fused k-feature
    gemm_hmma_kernel<2><<<gg, 256, SMEM_F>>>(
        hs + HX_HI, hs + HX_LO, hs + HW_BASE + 2 * 1048576,
        hs + HW_BASE + 3 * 1048576, bk, scratch + OFF_TK, proj,
        scratch + OFF_KMAX);
    // V GEMM (plain)
    gemm_hmma_kernel<0><<<gg, 256, SMEM0>>>(
        hs + HX_HI, hs + HX_LO, hs + HW_BASE + 4 * 1048576,
        hs + HW_BASE + 5 * 1048576, bv, scratch + OFF_V, nullptr, nullptr);

    ctx_kernel<<<64 * 8, 256>>>(mask);
    outhead_kernel<<<64 * 8, 256>>>(hs + HA_HI, hs + HA_LO);

    splitT_kernel<<<tg, tb>>>(Wo, hs + HW_BASE + 6 * 1048576,
                              hs + HW_BASE + 7 * 1048576);
    // O GEMM (plain) -> d_out
    gemm_hmma_kernel<0><<<gg, 256, SMEM0>>>(
        hs + HA_HI, hs + HA_LO, hs + HW_BASE + 6 * 1048576,
        hs + HW_BASE + 7 * 1048576, bo, (float*)d_out, nullptr, nullptr);
}